// round 3
// baseline (speedup 1.0000x reference)
#include <cuda_runtime.h>

// Problem constants
#define IN_CH 16
#define OUT_CH 32
#define KSZ 3
#define NUM_POINTS 3
#define NUM_INPUTS (IN_CH * KSZ * KSZ)   // 144
#define BATCH 8
#define H 32
#define W 32
#define N_PAIRS (NUM_INPUTS * OUT_CH)    // 4608

// Per-(i,o) piecewise coefficients, o-contiguous ([i][o])
__device__ float g_p1[N_PAIRS];
__device__ float g_s0[N_PAIRS];
__device__ float g_s1[N_PAIRS];
__device__ float g_base[OUT_CH];

// ---------------------------------------------------------------------------
// Kernel 1: turn (positions, values) into slope/threshold form.
//   y(x) = v1 + s*(x - p1),  s = (x>=p1 ? s1 : s0)
//   base[o] = sum_i v1[i][o]   (input-independent part of the sum)
// ---------------------------------------------------------------------------
__global__ void apc_coef_kernel(const float* __restrict__ pos,
                                const float* __restrict__ val) {
    int t = blockIdx.x * blockDim.x + threadIdx.x;
    if (t < N_PAIRS) {
        const float* p = pos + t * 3;
        const float* v = val + t * 3;
        float p0 = p[0], p1 = p[1], p2 = p[2];
        float v0 = v[0], v1 = v[1], v2 = v[2];
        g_p1[t] = p1;
        g_s0[t] = (v1 - v0) / (p1 - p0);
        g_s1[t] = (v2 - v1) / (p2 - p1);
    }
    if (blockIdx.x == 0 && threadIdx.x < OUT_CH) {
        float s = 0.f;
        #pragma unroll 16
        for (int i = 0; i < NUM_INPUTS; i++)
            s += val[(i * OUT_CH + threadIdx.x) * 3 + 1];
        g_base[threadIdx.x] = s;
    }
}

// ---------------------------------------------------------------------------
// Kernel 2: main compute — occupancy-oriented layout.
//   Block = (image b, output row y, half h): 16 output pixels.
//   512 threads = 16 warps. Warp w owns input channel w (9 i's, 27 coef regs).
//   lane = output channel o. Coefs in registers; x values are warp-uniform
//   broadcast LDS from a small staged tile. Cross-warp (channel) reduction
//   through padded smem partials.
//   __launch_bounds__(512, 2) caps regs at 64 -> 2 blocks = 32 warps/SM.
// ---------------------------------------------------------------------------
#define PX 16
#define TILE_COLS 18                      // 16 px + 2 halo
#define TILE_CH (3 * TILE_COLS)           // 54 floats per channel
#define TILE_ELEMS (IN_CH * TILE_CH)      // 864

__global__ __launch_bounds__(512, 2)
void apc_main_kernel(const float* __restrict__ x, float* __restrict__ out) {
    __shared__ float tile[TILE_ELEMS];                 // 3456 B
    __shared__ float partial[16][PX][33];              // 33792 B, padded

    const int tid = threadIdx.x;
    const int blk = blockIdx.x;
    const int b    = blk >> 6;            // image
    const int y    = (blk >> 1) & 31;     // output row
    const int x0   = (blk & 1) * PX;      // half-row start

    // ---- stage input rows y-1..y+1, cols x0-1..x0+16, zero halo ----
    const float* xb = x + b * (IN_CH * H * W);
    for (int idx = tid; idx < TILE_ELEMS; idx += 512) {
        int c   = idx / TILE_CH;
        int rem = idx - c * TILE_CH;
        int r   = rem / TILE_COLS;
        int col = rem - r * TILE_COLS;
        int gy = y + r - 1;
        int gx = x0 + col - 1;
        float v = 0.f;
        if ((unsigned)gy < (unsigned)H && (unsigned)gx < (unsigned)W)
            v = xb[(c * H + gy) * W + gx];
        tile[idx] = v;
    }

    // ---- this thread's 9 coefficient triples into registers ----
    const int w = tid >> 5;      // warp id = input channel
    const int o = tid & 31;      // lane id = output channel
    float cp1[9], cs0[9], cs1[9];
    {
        const int i0 = w * 9;
        #pragma unroll
        for (int j = 0; j < 9; j++) {
            int idx = (i0 + j) * OUT_CH + o;   // o-contiguous: coalesced
            cp1[j] = g_p1[idx];
            cs0[j] = g_s0[idx];
            cs1[j] = g_s1[idx];
        }
    }
    __syncthreads();

    // ---- main loop: 16 pixels x 9 i's, 32 o's per warp ----
    const float* tb = tile + w * TILE_CH;
    #pragma unroll 2
    for (int px = 0; px < PX; px++) {
        float acc0 = 0.f, acc1 = 0.f;
        #pragma unroll
        for (int j = 0; j < 9; j++) {
            const int kh = j / 3;
            const int kw = j % 3;
            // warp-uniform broadcast; compile-time immediate base
            float xv = tb[kh * TILE_COLS + kw + px];
            float d  = xv - cp1[j];
            float s  = (d >= 0.f) ? cs1[j] : cs0[j];
            if (j & 1) acc1 = fmaf(s, d, acc1);
            else       acc0 = fmaf(s, d, acc0);
        }
        partial[w][px][o] = acc0 + acc1;       // lanes contiguous: no conflict
    }
    __syncthreads();

    // ---- reduce 16 channel-partials per (px, o) and write out ----
    // thread q -> (o = q>>4, px = q&15); px contiguous in gmem: coalesced
    {
        const int px = tid & 15;
        const int oo = tid >> 4;
        float s = g_base[oo];
        #pragma unroll
        for (int ww = 0; ww < 16; ww++)
            s += partial[ww][px][oo];
        out[((b * OUT_CH + oo) * H + y) * W + x0 + px] = s;
    }
}

extern "C" void kernel_launch(void* const* d_in, const int* in_sizes, int n_in,
                              void* d_out, int out_size) {
    const float* x   = (const float*)d_in[0];
    const float* pos = (const float*)d_in[1];
    const float* val = (const float*)d_in[2];
    float* out = (float*)d_out;

    apc_coef_kernel<<<(N_PAIRS + 255) / 256, 256>>>(pos, val);
    apc_main_kernel<<<BATCH * H * 2, 512>>>(x, out);
}

// round 4
// speedup vs baseline: 1.1026x; 1.1026x over previous
#include <cuda_runtime.h>
#include <cstdint>

#define IN_CH 16
#define OUT_CH 32
#define BATCH 8
#define H 32
#define W 32

// Tile: 16 channels x 4 input rows (2 out rows + halo) x 34 cols (32 + halo)
#define TCOLS 34
#define TROWS 4
#define TCH (TROWS * TCOLS)          // 136
#define TILE_ELEMS (IN_CH * TCH)     // 2176

// Dynamic smem layout (bytes)
#define OFF_PK_NP1 0                  // [16][4][32] float2 = 16384
#define OFF_PK_S0  16384
#define OFF_PK_DSH 32768
#define OFF_S_NP1  49152              // [16][32] float = 2048
#define OFF_S_S0   51200
#define OFF_S_DSH  53248
#define OFF_VPART  55296              // [16][32] float = 2048
#define OFF_TILE   57344              // 2176 floats = 8704
#define OFF_OUTST  66048              // [64][33] floats = 8448
#define SMEM_BYTES 74496

__device__ __forceinline__ unsigned long long pack2(float lo, float hi) {
    unsigned long long r;
    asm("mov.b64 %0, {%1, %2};" : "=l"(r)
        : "r"(__float_as_uint(lo)), "r"(__float_as_uint(hi)));
    return r;
}
__device__ __forceinline__ void unpack2(unsigned long long v, float& lo, float& hi) {
    unsigned a, b;
    asm("mov.b64 {%0, %1}, %2;" : "=r"(a), "=r"(b) : "l"(v));
    lo = __uint_as_float(a); hi = __uint_as_float(b);
}
__device__ __forceinline__ unsigned long long add2(unsigned long long a, unsigned long long b) {
    unsigned long long r;
    asm("add.rn.f32x2 %0, %1, %2;" : "=l"(r) : "l"(a), "l"(b));
    return r;
}
__device__ __forceinline__ unsigned long long fma2(unsigned long long a, unsigned long long b,
                                                   unsigned long long c) {
    unsigned long long r;
    asm("fma.rn.f32x2 %0, %1, %2, %3;" : "=l"(r) : "l"(a), "l"(b), "l"(c));
    return r;
}

// Single fused kernel.
//   Block = (image b, output-row pair y0,y0+1): 64 output pixels, 512 threads.
//   Phase A: stage input tile (zero halo) into smem.
//   Phase B: thread (w,o) computes piecewise coefs for i = 9w..9w+8, channel w:
//            y_i(x) = v1 + s0*d + dsh*(d+|d|), d = x - p1, dsh = (s1-s0)/2.
//            Coefs for j=0..7 stored as i-PAIRS (float2) for packed f32x2 math;
//            j=8 stored scalar. Sum of v1 per (w,o) -> vpart (reduced in epilogue).
//   Main:    warp w owns 4 pixels (row r0=w>>3, cols 4*(w&7)..+3), loops all 16
//            channels: 18-value x window in regs (warp-uniform broadcast LDS),
//            4 packed i-pairs (LDS.64 coefs) + 1 scalar i per channel.
//   Epilogue: horizontal add of packed accumulators -> smem outstage (padded),
//            then coalesced, transposed global store + base term.
__global__ __launch_bounds__(512)
void apc_kernel(const float* __restrict__ x, const float* __restrict__ pos,
                const float* __restrict__ val, float* __restrict__ out) {
    extern __shared__ char sm[];
    float2* pk_np1 = (float2*)(sm + OFF_PK_NP1);
    float2* pk_s0  = (float2*)(sm + OFF_PK_S0);
    float2* pk_dsh = (float2*)(sm + OFF_PK_DSH);
    float*  s_np1  = (float*)(sm + OFF_S_NP1);
    float*  s_s0   = (float*)(sm + OFF_S_S0);
    float*  s_dsh  = (float*)(sm + OFF_S_DSH);
    float*  vpart  = (float*)(sm + OFF_VPART);
    float*  tile   = (float*)(sm + OFF_TILE);
    float*  outst  = (float*)(sm + OFF_OUTST);

    const int tid = threadIdx.x;
    const int w = tid >> 5;          // warp id
    const int o = tid & 31;          // lane = output channel
    const int b  = blockIdx.x >> 4;          // image
    const int y0 = (blockIdx.x & 15) << 1;   // first output row of the pair

    // ---- Phase A: stage tile (rows y0-1..y0+2, cols -1..32, zero halo) ----
    const float* xb = x + b * (IN_CH * H * W);
    for (int idx = tid; idx < TILE_ELEMS; idx += 512) {
        int c   = idx / TCH;
        int rem = idx - c * TCH;
        int r   = rem / TCOLS;
        int col = rem - r * TCOLS;
        int gy = y0 + r - 1;
        int gx = col - 1;
        float v = 0.f;
        if ((unsigned)gy < (unsigned)H && (unsigned)gx < (unsigned)W)
            v = xb[(c * H + gy) * W + gx];
        tile[idx] = v;
    }

    // ---- Phase B: coefficients for i = 9w+j, this lane's o ----
    {
        float vs = 0.f;
        #pragma unroll
        for (int j = 0; j < 9; j++) {
            int i = w * 9 + j;
            int base = (i * 32 + o) * 3;
            float p0 = pos[base], p1 = pos[base + 1], p2 = pos[base + 2];
            float v0 = val[base], v1 = val[base + 1], v2 = val[base + 2];
            float s0v = __fdividef(v1 - v0, p1 - p0);
            float s1v = __fdividef(v2 - v1, p2 - p1);
            float np1 = -p1;
            float dsh = 0.5f * (s1v - s0v);
            vs += v1;
            if (j < 8) {
                int pidx = (w * 4 + (j >> 1)) * 32 + o;
                int hf = j & 1;
                ((float*)&pk_np1[pidx])[hf] = np1;
                ((float*)&pk_s0 [pidx])[hf] = s0v;
                ((float*)&pk_dsh[pidx])[hf] = dsh;
            } else {
                s_np1[w * 32 + o] = np1;
                s_s0 [w * 32 + o] = s0v;
                s_dsh[w * 32 + o] = dsh;
            }
        }
        vpart[w * 32 + o] = vs;
    }
    __syncthreads();

    // ---- Main loop: warp w -> out row y0+r0, cols c0..c0+3 ----
    const int r0 = w >> 3;
    const int c0 = (w & 7) << 2;
    unsigned long long acc[4] = {0ull, 0ull, 0ull, 0ull};
    float accS[4] = {0.f, 0.f, 0.f, 0.f};
    const unsigned long long ABS2 = 0x7FFFFFFF7FFFFFFFull;

    const unsigned long long* pk1 = (const unsigned long long*)pk_np1;
    const unsigned long long* pk2 = (const unsigned long long*)pk_s0;
    const unsigned long long* pk3 = (const unsigned long long*)pk_dsh;

    #pragma unroll 2
    for (int c = 0; c < IN_CH; c++) {
        // x window: 3 rows x 6 cols, warp-uniform broadcast loads
        float xw[3][6];
        const float* tb = tile + c * TCH + r0 * TCOLS + c0;
        #pragma unroll
        for (int kh = 0; kh < 3; kh++)
            #pragma unroll
            for (int m = 0; m < 6; m++)
                xw[kh][m] = tb[kh * TCOLS + m];

        // 4 packed i-pairs: j = (2u, 2u+1)
        #pragma unroll
        for (int u = 0; u < 4; u++) {
            const int cidx = (c * 4 + u) * 32 + o;
            const unsigned long long np1p = pk1[cidx];
            const unsigned long long s0p  = pk2[cidx];
            const unsigned long long dshp = pk3[cidx];
            const int j0 = 2 * u,     j1 = 2 * u + 1;
            const int kh0 = j0 / 3,   kw0 = j0 % 3;
            const int kh1 = j1 / 3,   kw1 = j1 % 3;
            #pragma unroll
            for (int p = 0; p < 4; p++) {
                unsigned long long x2 = pack2(xw[kh0][p + kw0], xw[kh1][p + kw1]);
                unsigned long long d2 = add2(x2, np1p);
                unsigned long long e2 = add2(d2, d2 & ABS2);
                acc[p] = fma2(s0p, d2, acc[p]);
                acc[p] = fma2(dshp, e2, acc[p]);
            }
        }
        // scalar leftover j = 8 (kh=2, kw=2)
        {
            float np1 = s_np1[c * 32 + o];
            float s0v = s_s0 [c * 32 + o];
            float dsh = s_dsh[c * 32 + o];
            #pragma unroll
            for (int p = 0; p < 4; p++) {
                float d = xw[2][p + 2] + np1;
                float e = d + fabsf(d);
                accS[p] = fmaf(s0v, d, accS[p]);
                accS[p] = fmaf(dsh, e, accS[p]);
            }
        }
    }

    // ---- stage results: outstage[px][o], px = 4w+p ----
    #pragma unroll
    for (int p = 0; p < 4; p++) {
        float lo, hi;
        unpack2(acc[p], lo, hi);
        int px = (w << 2) + p;
        outst[px * 33 + o] = lo + hi + accS[p];
    }
    __syncthreads();

    // ---- epilogue: coalesced transposed store + base term ----
    {
        const int col = tid & 31;
        const int ob  = tid >> 5;         // 0..15
        #pragma unroll
        for (int oh = 0; oh < 2; oh++) {
            int oo = ob + (oh << 4);
            float vb = 0.f;
            #pragma unroll
            for (int ww = 0; ww < 16; ww++)
                vb += vpart[ww * 32 + oo];     // warp-uniform broadcast
            #pragma unroll
            for (int r = 0; r < 2; r++) {
                int px = (r << 5) + col;
                out[((b * OUT_CH + oo) * H + (y0 + r)) * W + col] =
                    outst[px * 33 + oo] + vb;  // stride-33: conflict-free
            }
        }
    }
}

extern "C" void kernel_launch(void* const* d_in, const int* in_sizes, int n_in,
                              void* d_out, int out_size) {
    const float* x   = (const float*)d_in[0];
    const float* pos = (const float*)d_in[1];
    const float* val = (const float*)d_in[2];
    float* out = (float*)d_out;

    cudaFuncSetAttribute(apc_kernel, cudaFuncAttributeMaxDynamicSharedMemorySize,
                         SMEM_BYTES);
    apc_kernel<<<BATCH * (H / 2), 512, SMEM_BYTES>>>(x, pos, val, out);
}